// round 15
// baseline (speedup 1.0000x reference)
#include <cuda_runtime.h>

// x: (32,3,16,32,32) fp32; weight: (3,16,3,3,3); bias scalar; out: (32,1,31,63,63)
// ConvTranspose3d s=2 p=1 k=3: per dim even o -> tap k=1 (i=o/2);
// odd o -> k=0 (i=(o+1)/2), k=2 (i=(o-1)/2). All in-range (od<=30, oh/ow<=62).

#define DIN 16
#define HIN 32
#define WIN 32
#define XCH (DIN*HIN*WIN)   // 16384
#define XB  (3*XCH)         // 49152
#define WSH (16*3*3*12)     // sw[oc][kd][kh][slot], slot=ic*3+kw (9 used, pad 12)
#define LOG2E 1.4426950408889634f
#define LN2   0.6931471805599453f

__device__ __forceinline__ float ex2f(float x) {
    float r; asm("ex2.approx.ftz.f32 %0, %1;" : "=f"(r) : "f"(x)); return r;
}
__device__ __forceinline__ float lg2f(float x) {
    float r; asm("lg2.approx.ftz.f32 %0, %1;" : "=f"(r) : "f"(x)); return r;
}

// Weights pre-scaled by log2(e): conv accumulators live in log2 domain; exp = one EX2.
__device__ __forceinline__ void load_weights(const float* __restrict__ w, float* sw) {
    // src w[ic*432 + oc*27 + kd*9 + kh*3 + kw]
    for (int i = threadIdx.x; i < 1296; i += 128) {
        int ic = i / 432;  int r = i - ic * 432;
        int oc = r / 27;   int tap = r - oc * 27;
        int kd = tap / 9;  int t2 = tap - kd * 9;
        int kh = t2 / 3;   int kw = t2 - kh * 3;
        sw[((oc * 3 + kd) * 3 + kh) * 12 + ic * 3 + kw] = w[i] * LOG2E;
    }
}

// s = sum_oc e^conv. Pure MUFU epilogue (LG2/EX2/RCP):
__device__ __forceinline__ float finish(float s, float bv) {
    float l2 = lg2f(s);
    float e  = ex2f(-l2 - 3.0f * LOG2E);
    float l  = l2 * LN2;
    float h  = __fdividef(l, fmaf(e, 6.f, 6.f));
    return fminf(fmaxf(h - bv, -1.f), 1.f);
}

// ---------------- width-8 path (classes with ND*NH <= 2) ----------------
// Lane c = lane&7 handles ow = 8c..8c+7 (c==7: ow 63 masked). 4 rows per warp.
template<int ND, int NH>
__device__ __forceinline__ void run_oct(
    const float* __restrict__ xb, const float* __restrict__ sw,
    float* __restrict__ op, int id0, int id1, int ih0, int ih1, int c, float bv)
{
    float xv[ND][NH][3][5];
    int iw0 = 4 * c;
    #pragma unroll
    for (int a = 0; a < ND; a++) {
        int idv = (a == 0) ? id0 : id1;
        #pragma unroll
        for (int h = 0; h < NH; h++) {
            int ihv = (h == 0) ? ih0 : ih1;
            const float* p = xb + idv * (HIN * WIN) + ihv * WIN;
            #pragma unroll
            for (int ic = 0; ic < 3; ic++) {
                float4 t = __ldg((const float4*)(p + ic * XCH + iw0));  // 16B aligned
                xv[a][h][ic][0] = t.x; xv[a][h][ic][1] = t.y;
                xv[a][h][ic][2] = t.z; xv[a][h][ic][3] = t.w;
                // x[iw0+4] == lane (c+1)'s t.x; c==7 gets other-row garbage (masked)
                xv[a][h][ic][4] = __shfl_down_sync(0xffffffffu, t.x, 1);
            }
        }
    }

    float s[8];
    #pragma unroll
    for (int k = 0; k < 8; k++) s[k] = 0.f;

    #pragma unroll
    for (int oc = 0; oc < 16; oc++) {
        float v[8];
        #pragma unroll
        for (int k = 0; k < 8; k++) v[k] = 0.f;
        #pragma unroll
        for (int a = 0; a < ND; a++) {
            const int KD = (ND == 1) ? 1 : a * 2;
            #pragma unroll
            for (int h = 0; h < NH; h++) {
                const int KH = (NH == 1) ? 1 : h * 2;
                const float* g = sw + ((oc * 3 + KD) * 3 + KH) * 12;
                float4 A = *(const float4*)g;
                float4 B = *(const float4*)(g + 4);
                float  C = g[8];
                #pragma unroll
                for (int t = 0; t < 4; t++) {
                    float x0t = xv[a][h][0][t], x1t = xv[a][h][1][t], x2t = xv[a][h][2][t];
                    float x0n = xv[a][h][0][t+1], x1n = xv[a][h][1][t+1], x2n = xv[a][h][2][t+1];
                    v[2*t]   = fmaf(A.y, x0t, v[2*t]);
                    v[2*t]   = fmaf(B.x, x1t, v[2*t]);
                    v[2*t]   = fmaf(B.w, x2t, v[2*t]);
                    v[2*t+1] = fmaf(A.x, x0n, v[2*t+1]);
                    v[2*t+1] = fmaf(A.w, x1n, v[2*t+1]);
                    v[2*t+1] = fmaf(B.z, x2n, v[2*t+1]);
                    v[2*t+1] = fmaf(A.z, x0t, v[2*t+1]);
                    v[2*t+1] = fmaf(B.y, x1t, v[2*t+1]);
                    v[2*t+1] = fmaf(C,   x2t, v[2*t+1]);
                }
            }
        }
        #pragma unroll
        for (int k = 0; k < 8; k++) s[k] += ex2f(v[k]);   // v in log2 domain
    }

    int wb = 8 * c;
    #pragma unroll
    for (int k = 0; k < 7; k++) op[wb + k] = finish(s[k], bv);
    if (c < 7) op[wb + 7] = finish(s[7], bv);
}

// ---------------- width-4 path (class 3: odd od, odd oh) ----------------
__device__ __forceinline__ void run_quad22(
    const float* __restrict__ xb, const float* __restrict__ sw,
    float* __restrict__ op, int id0, int id1, int ih0, int ih1, int c, float bv)
{
    float xv[2][2][3][3];
    int iw0 = 2 * c;
    #pragma unroll
    for (int a = 0; a < 2; a++) {
        int idv = (a == 0) ? id0 : id1;
        #pragma unroll
        for (int h = 0; h < 2; h++) {
            int ihv = (h == 0) ? ih0 : ih1;
            const float* p = xb + idv * (HIN * WIN) + ihv * WIN;
            #pragma unroll
            for (int ic = 0; ic < 3; ic++) {
                float2 t = __ldg((const float2*)(p + ic * XCH + iw0));
                xv[a][h][ic][0] = t.x;
                xv[a][h][ic][1] = t.y;
                xv[a][h][ic][2] = __shfl_down_sync(0xffffffffu, t.x, 1);
            }
        }
    }

    float s0 = 0.f, s1 = 0.f, s2 = 0.f, s3 = 0.f;
    #pragma unroll
    for (int oc = 0; oc < 16; oc++) {
        float v0 = 0.f, v1 = 0.f, v2 = 0.f, v3 = 0.f;
        #pragma unroll
        for (int a = 0; a < 2; a++) {
            const int KD = a * 2;
            #pragma unroll
            for (int h = 0; h < 2; h++) {
                const int KH = h * 2;
                const float* g = sw + ((oc * 3 + KD) * 3 + KH) * 12;
                float4 A = *(const float4*)g;
                float4 B = *(const float4*)(g + 4);
                float  C = g[8];
                float x00 = xv[a][h][0][0], x01 = xv[a][h][0][1], x02 = xv[a][h][0][2];
                float x10 = xv[a][h][1][0], x11 = xv[a][h][1][1], x12 = xv[a][h][1][2];
                float x20 = xv[a][h][2][0], x21 = xv[a][h][2][1], x22 = xv[a][h][2][2];
                v0 = fmaf(A.y, x00, v0); v0 = fmaf(B.x, x10, v0); v0 = fmaf(B.w, x20, v0);
                v2 = fmaf(A.y, x01, v2); v2 = fmaf(B.x, x11, v2); v2 = fmaf(B.w, x21, v2);
                v1 = fmaf(A.x, x01, v1); v1 = fmaf(A.w, x11, v1); v1 = fmaf(B.z, x21, v1);
                v1 = fmaf(A.z, x00, v1); v1 = fmaf(B.y, x10, v1); v1 = fmaf(C,   x20, v1);
                v3 = fmaf(A.x, x02, v3); v3 = fmaf(A.w, x12, v3); v3 = fmaf(B.z, x22, v3);
                v3 = fmaf(A.z, x01, v3); v3 = fmaf(B.y, x11, v3); v3 = fmaf(C,   x21, v3);
            }
        }
        s0 += ex2f(v0); s1 += ex2f(v1); s2 += ex2f(v2); s3 += ex2f(v3);
    }

    int wb = 4 * c;
    op[wb]     = finish(s0, bv);
    op[wb + 1] = finish(s1, bv);
    op[wb + 2] = finish(s2, bv);
    if (wb + 3 < 63) op[wb + 3] = finish(s3, bv);
}

// Merged kernel, 128-thread blocks, min 8 blocks/SM (forces regs <= 64).
// CLASS STRIPING: virtual block id = bid*2641 mod 4836 (2641 coprime to 4836)
// spreads the 4 class ranges pseudo-uniformly across physical block ids, so each
// SM co-hosts MUFU-heavy (cls0/1/2: 8 EX2 per 36 FMA) and FMA-heavy (cls3:
// 288 FMA/output) CTAs -> both pipes stay fed instead of one saturating per SM.
// Virtual ranges (same as before):
//   [0,1860):     cls3, width-4,  8 rows/block (14880 rows)
//   [1860,2884):  cls0, width-8, 16 rows/block (16384 rows)
//   [2884,3876):  cls1, width-8 (15872 rows)
//   [3876,4836):  cls2, width-8 (15360 rows)
__global__ __launch_bounds__(128, 8)
void convT_lse_v15(const float* __restrict__ x, const float* __restrict__ w,
                   const float* __restrict__ bias, float* __restrict__ out)
{
    __shared__ __align__(16) float sw[WSH];
    load_weights(w, sw);
    __syncthreads();

    int warp = threadIdx.x >> 5, lane = threadIdx.x & 31;
    float bv = __ldg(bias);
    int blk = (int)(((long long)blockIdx.x * 2641) % 4836);   // stride permutation

    if (blk < 1860) {
        int half = lane >> 4, c = lane & 15;
        int r = (blk * 4 + warp) * 2 + half;
        const int per_b = 15 * 31;
        int b = r / per_b; int rem = r - b * per_b;
        int idd = rem / 31; int ihh = rem - idd * 31;
        int od = 2 * idd + 1, oh = 2 * ihh + 1;
        const float* xb = x + (size_t)b * XB;
        float* op = out + ((size_t)(b * 31 + od) * 63 + oh) * 63;
        int id0 = (od + 1) >> 1, id1 = (od - 1) >> 1;
        int ih0 = (oh + 1) >> 1, ih1 = (oh - 1) >> 1;
        run_quad22(xb, sw, op, id0, id1, ih0, ih1, c, bv);
        return;
    }

    int rloc = lane >> 3, c = lane & 7;
    int cls, rb;
    if (blk < 2884)      { cls = 0; rb = (blk - 1860) * 16; }
    else if (blk < 3876) { cls = 1; rb = (blk - 2884) * 16; }
    else                 { cls = 2; rb = (blk - 3876) * 16; }
    int r = rb + warp * 4 + rloc;

    int pd = (cls == 2), ph = (cls == 1);
    int nhc = ph ? 31 : 32;
    int per_b = (pd ? 15 : 16) * nhc;
    int b = r / per_b; int rem = r - b * per_b;
    int idd = rem / nhc; int ihh = rem - idd * nhc;
    int od = 2 * idd + pd, oh = 2 * ihh + ph;

    const float* xb = x + (size_t)b * XB;
    float* op = out + ((size_t)(b * 31 + od) * 63 + oh) * 63;

    int id0, id1 = 0, ih0, ih1 = 0;
    if (pd) { id0 = (od + 1) >> 1; id1 = (od - 1) >> 1; } else id0 = od >> 1;
    if (ph) { ih0 = (oh + 1) >> 1; ih1 = (oh - 1) >> 1; } else ih0 = oh >> 1;

    if (cls == 0)      run_oct<1, 1>(xb, sw, op, id0, id1, ih0, ih1, c, bv);
    else if (cls == 1) run_oct<1, 2>(xb, sw, op, id0, id1, ih0, ih1, c, bv);
    else               run_oct<2, 1>(xb, sw, op, id0, id1, ih0, ih1, c, bv);
}

extern "C" void kernel_launch(void* const* d_in, const int* in_sizes, int n_in,
                              void* d_out, int out_size)
{
    const float* x    = (const float*)d_in[0];
    const float* w    = (const float*)d_in[1];
    const float* bias = (const float*)d_in[2];
    float* out        = (float*)d_out;

    convT_lse_v15<<<4836, 128>>>(x, w, bias, out);
}

// round 16
// speedup vs baseline: 1.4012x; 1.4012x over previous
#include <cuda_runtime.h>

// x: (32,3,16,32,32) fp32; weight: (3,16,3,3,3); bias scalar; out: (32,1,31,63,63)
// ConvTranspose3d s=2 p=1 k=3: per dim even o -> tap k=1 (i=o/2);
// odd o -> k=0 (i=(o+1)/2), k=2 (i=(o-1)/2). All in-range (od<=30, oh/ow<=62).

#define DIN 16
#define HIN 32
#define WIN 32
#define XCH (DIN*HIN*WIN)   // 16384
#define XB  (3*XCH)         // 49152
#define WSH (16*3*3*12)     // sw[oc][kd][kh][slot], slot=ic*3+kw (9 used, pad 12)
#define LOG2E 1.4426950408889634f
#define LN2   0.6931471805599453f

__device__ __forceinline__ float ex2f(float x) {
    float r; asm("ex2.approx.ftz.f32 %0, %1;" : "=f"(r) : "f"(x)); return r;
}
__device__ __forceinline__ float lg2f(float x) {
    float r; asm("lg2.approx.ftz.f32 %0, %1;" : "=f"(r) : "f"(x)); return r;
}

// Weights pre-scaled by log2(e): conv accumulators live in log2 domain; exp = one EX2.
__device__ __forceinline__ void load_weights(const float* __restrict__ w, float* sw) {
    // src w[ic*432 + oc*27 + kd*9 + kh*3 + kw]
    for (int i = threadIdx.x; i < 1296; i += 128) {
        int ic = i / 432;  int r = i - ic * 432;
        int oc = r / 27;   int tap = r - oc * 27;
        int kd = tap / 9;  int t2 = tap - kd * 9;
        int kh = t2 / 3;   int kw = t2 - kh * 3;
        sw[((oc * 3 + kd) * 3 + kh) * 12 + ic * 3 + kw] = w[i] * LOG2E;
    }
}

// s = sum_oc e^conv. Pure MUFU epilogue (LG2/EX2/RCP):
__device__ __forceinline__ float finish(float s, float bv) {
    float l2 = lg2f(s);
    float e  = ex2f(-l2 - 3.0f * LOG2E);
    float l  = l2 * LN2;
    float h  = __fdividef(l, fmaf(e, 6.f, 6.f));
    return fminf(fmaxf(h - bv, -1.f), 1.f);
}

// ---------------- width-8 path (classes with ND*NH <= 2) ----------------
// Lane c = lane&7 handles ow = 8c..8c+7 (c==7: ow 63 masked). 4 rows per warp.
template<int ND, int NH>
__device__ __forceinline__ void run_oct(
    const float* __restrict__ xb, const float* __restrict__ sw,
    float* __restrict__ op, int id0, int id1, int ih0, int ih1, int c, float bv)
{
    float xv[ND][NH][3][5];
    int iw0 = 4 * c;
    #pragma unroll
    for (int a = 0; a < ND; a++) {
        int idv = (a == 0) ? id0 : id1;
        #pragma unroll
        for (int h = 0; h < NH; h++) {
            int ihv = (h == 0) ? ih0 : ih1;
            const float* p = xb + idv * (HIN * WIN) + ihv * WIN;
            #pragma unroll
            for (int ic = 0; ic < 3; ic++) {
                float4 t = __ldg((const float4*)(p + ic * XCH + iw0));  // 16B aligned
                xv[a][h][ic][0] = t.x; xv[a][h][ic][1] = t.y;
                xv[a][h][ic][2] = t.z; xv[a][h][ic][3] = t.w;
                // x[iw0+4] == lane (c+1)'s t.x; c==7 gets other-row garbage (masked)
                xv[a][h][ic][4] = __shfl_down_sync(0xffffffffu, t.x, 1);
            }
        }
    }

    float s[8];
    #pragma unroll
    for (int k = 0; k < 8; k++) s[k] = 0.f;

    #pragma unroll
    for (int oc = 0; oc < 16; oc++) {
        float v[8];
        #pragma unroll
        for (int k = 0; k < 8; k++) v[k] = 0.f;
        #pragma unroll
        for (int a = 0; a < ND; a++) {
            const int KD = (ND == 1) ? 1 : a * 2;
            #pragma unroll
            for (int h = 0; h < NH; h++) {
                const int KH = (NH == 1) ? 1 : h * 2;
                const float* g = sw + ((oc * 3 + KD) * 3 + KH) * 12;
                float4 A = *(const float4*)g;
                float4 B = *(const float4*)(g + 4);
                float  C = g[8];
                #pragma unroll
                for (int t = 0; t < 4; t++) {
                    float x0t = xv[a][h][0][t], x1t = xv[a][h][1][t], x2t = xv[a][h][2][t];
                    float x0n = xv[a][h][0][t+1], x1n = xv[a][h][1][t+1], x2n = xv[a][h][2][t+1];
                    v[2*t]   = fmaf(A.y, x0t, v[2*t]);
                    v[2*t]   = fmaf(B.x, x1t, v[2*t]);
                    v[2*t]   = fmaf(B.w, x2t, v[2*t]);
                    v[2*t+1] = fmaf(A.x, x0n, v[2*t+1]);
                    v[2*t+1] = fmaf(A.w, x1n, v[2*t+1]);
                    v[2*t+1] = fmaf(B.z, x2n, v[2*t+1]);
                    v[2*t+1] = fmaf(A.z, x0t, v[2*t+1]);
                    v[2*t+1] = fmaf(B.y, x1t, v[2*t+1]);
                    v[2*t+1] = fmaf(C,   x2t, v[2*t+1]);
                }
            }
        }
        #pragma unroll
        for (int k = 0; k < 8; k++) s[k] += ex2f(v[k]);   // v in log2 domain
    }

    int wb = 8 * c;
    #pragma unroll
    for (int k = 0; k < 7; k++) op[wb + k] = finish(s[k], bv);
    if (c < 7) op[wb + 7] = finish(s[7], bv);
}

// ---------------- width-4 path (class 3: odd od, odd oh) ----------------
__device__ __forceinline__ void run_quad22(
    const float* __restrict__ xb, const float* __restrict__ sw,
    float* __restrict__ op, int id0, int id1, int ih0, int ih1, int c, float bv)
{
    float xv[2][2][3][3];
    int iw0 = 2 * c;
    #pragma unroll
    for (int a = 0; a < 2; a++) {
        int idv = (a == 0) ? id0 : id1;
        #pragma unroll
        for (int h = 0; h < 2; h++) {
            int ihv = (h == 0) ? ih0 : ih1;
            const float* p = xb + idv * (HIN * WIN) + ihv * WIN;
            #pragma unroll
            for (int ic = 0; ic < 3; ic++) {
                float2 t = __ldg((const float2*)(p + ic * XCH + iw0));
                xv[a][h][ic][0] = t.x;
                xv[a][h][ic][1] = t.y;
                xv[a][h][ic][2] = __shfl_down_sync(0xffffffffu, t.x, 1);
            }
        }
    }

    float s0 = 0.f, s1 = 0.f, s2 = 0.f, s3 = 0.f;
    #pragma unroll
    for (int oc = 0; oc < 16; oc++) {
        float v0 = 0.f, v1 = 0.f, v2 = 0.f, v3 = 0.f;
        #pragma unroll
        for (int a = 0; a < 2; a++) {
            const int KD = a * 2;
            #pragma unroll
            for (int h = 0; h < 2; h++) {
                const int KH = h * 2;
                const float* g = sw + ((oc * 3 + KD) * 3 + KH) * 12;
                float4 A = *(const float4*)g;
                float4 B = *(const float4*)(g + 4);
                float  C = g[8];
                float x00 = xv[a][h][0][0], x01 = xv[a][h][0][1], x02 = xv[a][h][0][2];
                float x10 = xv[a][h][1][0], x11 = xv[a][h][1][1], x12 = xv[a][h][1][2];
                float x20 = xv[a][h][2][0], x21 = xv[a][h][2][1], x22 = xv[a][h][2][2];
                v0 = fmaf(A.y, x00, v0); v0 = fmaf(B.x, x10, v0); v0 = fmaf(B.w, x20, v0);
                v2 = fmaf(A.y, x01, v2); v2 = fmaf(B.x, x11, v2); v2 = fmaf(B.w, x21, v2);
                v1 = fmaf(A.x, x01, v1); v1 = fmaf(A.w, x11, v1); v1 = fmaf(B.z, x21, v1);
                v1 = fmaf(A.z, x00, v1); v1 = fmaf(B.y, x10, v1); v1 = fmaf(C,   x20, v1);
                v3 = fmaf(A.x, x02, v3); v3 = fmaf(A.w, x12, v3); v3 = fmaf(B.z, x22, v3);
                v3 = fmaf(A.z, x01, v3); v3 = fmaf(B.y, x11, v3); v3 = fmaf(C,   x21, v3);
            }
        }
        s0 += ex2f(v0); s1 += ex2f(v1); s2 += ex2f(v2); s3 += ex2f(v3);
    }

    int wb = 4 * c;
    op[wb]     = finish(s0, bv);
    op[wb + 1] = finish(s1, bv);
    op[wb + 2] = finish(s2, bv);
    if (wb + 3 < 63) op[wb + 3] = finish(s3, bv);
}

// Merged kernel, 128-thread blocks, min 8 blocks/SM (regs <= 64).
// CONTIGUOUS class ranges (segregation is load-bearing: R15 striping thrashed
// I$ and cost 20us). Longest-job-first order: cls3 > cls2 > cls1 > cls0 so the
// final partial wave contains only the cheapest (cls0) blocks.
//   [0,1860):     cls3, width-4,  8 rows/block (14880 rows)
//   [1860,2340):  cls2, width-8, 16 rows/block (15360 rows)
//   [2340,3332):  cls1, width-8 (15872 rows)
//   [3332,4836):  cls0... (see ranges below: cls2=480, cls1=992? no) — computed:
//   cls2 rows 15360 -> 960 blocks? 15360/16=960. cls1 15872/16=992. cls0 16384/16=1024.
//   [1860,2820): cls2 (960)   [2820,3812): cls1 (992)   [3812,4836): cls0 (1024)
__global__ __launch_bounds__(128, 8)
void convT_lse_v16(const float* __restrict__ x, const float* __restrict__ w,
                   const float* __restrict__ bias, float* __restrict__ out)
{
    __shared__ __align__(16) float sw[WSH];
    load_weights(w, sw);
    __syncthreads();

    int warp = threadIdx.x >> 5, lane = threadIdx.x & 31;
    float bv = __ldg(bias);
    int blk = blockIdx.x;

    if (blk < 1860) {
        // class 3 (odd od, odd oh), width 4, 8 rows/block
        int half = lane >> 4, c = lane & 15;
        int r = (blk * 4 + warp) * 2 + half;
        const int per_b = 15 * 31;
        int b = r / per_b; int rem = r - b * per_b;
        int idd = rem / 31; int ihh = rem - idd * 31;
        int od = 2 * idd + 1, oh = 2 * ihh + 1;
        const float* xb = x + (size_t)b * XB;
        float* op = out + ((size_t)(b * 31 + od) * 63 + oh) * 63;
        int id0 = (od + 1) >> 1, id1 = (od - 1) >> 1;
        int ih0 = (oh + 1) >> 1, ih1 = (oh - 1) >> 1;
        run_quad22(xb, sw, op, id0, id1, ih0, ih1, c, bv);
        return;
    }

    // width-8 classes, 16 rows/block; order: cls2 (heavier), cls1, cls0 (lightest last)
    int rloc = lane >> 3, c = lane & 7;
    int cls, rb;
    if (blk < 2820)      { cls = 2; rb = (blk - 1860) * 16; }   // 960 blocks
    else if (blk < 3812) { cls = 1; rb = (blk - 2820) * 16; }   // 992 blocks
    else                 { cls = 0; rb = (blk - 3812) * 16; }   // 1024 blocks
    int r = rb + warp * 4 + rloc;

    int pd = (cls == 2), ph = (cls == 1);
    int nhc = ph ? 31 : 32;
    int per_b = (pd ? 15 : 16) * nhc;
    int b = r / per_b; int rem = r - b * per_b;
    int idd = rem / nhc; int ihh = rem - idd * nhc;
    int od = 2 * idd + pd, oh = 2 * ihh + ph;

    const float* xb = x + (size_t)b * XB;
    float* op = out + ((size_t)(b * 31 + od) * 63 + oh) * 63;

    int id0, id1 = 0, ih0, ih1 = 0;
    if (pd) { id0 = (od + 1) >> 1; id1 = (od - 1) >> 1; } else id0 = od >> 1;
    if (ph) { ih0 = (oh + 1) >> 1; ih1 = (oh - 1) >> 1; } else ih0 = oh >> 1;

    if (cls == 0)      run_oct<1, 1>(xb, sw, op, id0, id1, ih0, ih1, c, bv);
    else if (cls == 1) run_oct<1, 2>(xb, sw, op, id0, id1, ih0, ih1, c, bv);
    else               run_oct<2, 1>(xb, sw, op, id0, id1, ih0, ih1, c, bv);
}

extern "C" void kernel_launch(void* const* d_in, const int* in_sizes, int n_in,
                              void* d_out, int out_size)
{
    const float* x    = (const float*)d_in[0];
    const float* w    = (const float*)d_in[1];
    const float* bias = (const float*)d_in[2];
    float* out        = (float*)d_out;

    convT_lse_v16<<<4836, 128>>>(x, w, bias, out);
}

// round 17
// speedup vs baseline: 1.4494x; 1.0344x over previous
#include <cuda_runtime.h>

// x: (32,3,16,32,32) fp32; weight: (3,16,3,3,3); bias scalar; out: (32,1,31,63,63)
// ConvTranspose3d s=2 p=1 k=3: per dim even o -> tap k=1 (i=o/2);
// odd o -> k=0 (i=(o+1)/2), k=2 (i=(o-1)/2). All in-range (od<=30, oh/ow<=62).

#define DIN 16
#define HIN 32
#define WIN 32
#define XCH (DIN*HIN*WIN)   // 16384
#define XB  (3*XCH)         // 49152
#define WSH (16*3*3*12)     // sw[oc][kd][kh][slot], slot=ic*3+kw (9 used, pad 12)
#define LOG2E 1.4426950408889634f
#define LN2   0.6931471805599453f

// Iteration counts per class (iter = 8 rows for cls3, 16 rows for cls0/1/2)
#define N3 1860
#define N2 960
#define N1 992
#define N0 1024

__device__ float g_sw[WSH];   // prepacked, log2e-scaled weights (zero-init pads)
__device__ int   g_ctr[4];    // per-class iteration counters

__device__ __forceinline__ float ex2f(float x) {
    float r; asm("ex2.approx.ftz.f32 %0, %1;" : "=f"(r) : "f"(x)); return r;
}
__device__ __forceinline__ float lg2f(float x) {
    float r; asm("lg2.approx.ftz.f32 %0, %1;" : "=f"(r) : "f"(x)); return r;
}

__device__ __forceinline__ float finish(float s, float bv) {
    float l2 = lg2f(s);
    float e  = ex2f(-l2 - 3.0f * LOG2E);
    float l  = l2 * LN2;
    float h  = __fdividef(l, fmaf(e, 6.f, 6.f));
    return fminf(fmaxf(h - bv, -1.f), 1.f);
}

// ---- prep: zero counters + prepack weights (runs once per graph replay) ----
__global__ void convT_prep(const float* __restrict__ w)
{
    int tid = threadIdx.x;
    if (tid < 4) g_ctr[tid] = 0;
    for (int i = tid; i < 1296; i += 128) {
        int ic = i / 432;  int r = i - ic * 432;
        int oc = r / 27;   int tap = r - oc * 27;
        int kd = tap / 9;  int t2 = tap - kd * 9;
        int kh = t2 / 3;   int kw = t2 - kh * 3;
        g_sw[((oc * 3 + kd) * 3 + kh) * 12 + ic * 3 + kw] = w[i] * LOG2E;
    }
}

// ---------------- width-8 path (classes with ND*NH <= 2) ----------------
template<int ND, int NH>
__device__ __forceinline__ void run_oct(
    const float* __restrict__ xb, const float* __restrict__ sw,
    float* __restrict__ op, int id0, int id1, int ih0, int ih1, int c, float bv)
{
    float xv[ND][NH][3][5];
    int iw0 = 4 * c;
    #pragma unroll
    for (int a = 0; a < ND; a++) {
        int idv = (a == 0) ? id0 : id1;
        #pragma unroll
        for (int h = 0; h < NH; h++) {
            int ihv = (h == 0) ? ih0 : ih1;
            const float* p = xb + idv * (HIN * WIN) + ihv * WIN;
            #pragma unroll
            for (int ic = 0; ic < 3; ic++) {
                float4 t = __ldg((const float4*)(p + ic * XCH + iw0));
                xv[a][h][ic][0] = t.x; xv[a][h][ic][1] = t.y;
                xv[a][h][ic][2] = t.z; xv[a][h][ic][3] = t.w;
                xv[a][h][ic][4] = __shfl_down_sync(0xffffffffu, t.x, 1);
            }
        }
    }

    float s[8];
    #pragma unroll
    for (int k = 0; k < 8; k++) s[k] = 0.f;

    #pragma unroll
    for (int oc = 0; oc < 16; oc++) {
        float v[8];
        #pragma unroll
        for (int k = 0; k < 8; k++) v[k] = 0.f;
        #pragma unroll
        for (int a = 0; a < ND; a++) {
            const int KD = (ND == 1) ? 1 : a * 2;
            #pragma unroll
            for (int h = 0; h < NH; h++) {
                const int KH = (NH == 1) ? 1 : h * 2;
                const float* g = sw + ((oc * 3 + KD) * 3 + KH) * 12;
                float4 A = *(const float4*)g;
                float4 B = *(const float4*)(g + 4);
                float  C = g[8];
                #pragma unroll
                for (int t = 0; t < 4; t++) {
                    float x0t = xv[a][h][0][t], x1t = xv[a][h][1][t], x2t = xv[a][h][2][t];
                    float x0n = xv[a][h][0][t+1], x1n = xv[a][h][1][t+1], x2n = xv[a][h][2][t+1];
                    v[2*t]   = fmaf(A.y, x0t, v[2*t]);
                    v[2*t]   = fmaf(B.x, x1t, v[2*t]);
                    v[2*t]   = fmaf(B.w, x2t, v[2*t]);
                    v[2*t+1] = fmaf(A.x, x0n, v[2*t+1]);
                    v[2*t+1] = fmaf(A.w, x1n, v[2*t+1]);
                    v[2*t+1] = fmaf(B.z, x2n, v[2*t+1]);
                    v[2*t+1] = fmaf(A.z, x0t, v[2*t+1]);
                    v[2*t+1] = fmaf(B.y, x1t, v[2*t+1]);
                    v[2*t+1] = fmaf(C,   x2t, v[2*t+1]);
                }
            }
        }
        #pragma unroll
        for (int k = 0; k < 8; k++) s[k] += ex2f(v[k]);
    }

    int wb = 8 * c;
    #pragma unroll
    for (int k = 0; k < 7; k++) op[wb + k] = finish(s[k], bv);
    if (c < 7) op[wb + 7] = finish(s[7], bv);
}

// ---------------- width-4 path (class 3: odd od, odd oh) ----------------
__device__ __forceinline__ void run_quad22(
    const float* __restrict__ xb, const float* __restrict__ sw,
    float* __restrict__ op, int id0, int id1, int ih0, int ih1, int c, float bv)
{
    float xv[2][2][3][3];
    int iw0 = 2 * c;
    #pragma unroll
    for (int a = 0; a < 2; a++) {
        int idv = (a == 0) ? id0 : id1;
        #pragma unroll
        for (int h = 0; h < 2; h++) {
            int ihv = (h == 0) ? ih0 : ih1;
            const float* p = xb + idv * (HIN * WIN) + ihv * WIN;
            #pragma unroll
            for (int ic = 0; ic < 3; ic++) {
                float2 t = __ldg((const float2*)(p + ic * XCH + iw0));
                xv[a][h][ic][0] = t.x;
                xv[a][h][ic][1] = t.y;
                xv[a][h][ic][2] = __shfl_down_sync(0xffffffffu, t.x, 1);
            }
        }
    }

    float s0 = 0.f, s1 = 0.f, s2 = 0.f, s3 = 0.f;
    #pragma unroll
    for (int oc = 0; oc < 16; oc++) {
        float v0 = 0.f, v1 = 0.f, v2 = 0.f, v3 = 0.f;
        #pragma unroll
        for (int a = 0; a < 2; a++) {
            const int KD = a * 2;
            #pragma unroll
            for (int h = 0; h < 2; h++) {
                const int KH = h * 2;
                const float* g = sw + ((oc * 3 + KD) * 3 + KH) * 12;
                float4 A = *(const float4*)g;
                float4 B = *(const float4*)(g + 4);
                float  C = g[8];
                float x00 = xv[a][h][0][0], x01 = xv[a][h][0][1], x02 = xv[a][h][0][2];
                float x10 = xv[a][h][1][0], x11 = xv[a][h][1][1], x12 = xv[a][h][1][2];
                float x20 = xv[a][h][2][0], x21 = xv[a][h][2][1], x22 = xv[a][h][2][2];
                v0 = fmaf(A.y, x00, v0); v0 = fmaf(B.x, x10, v0); v0 = fmaf(B.w, x20, v0);
                v2 = fmaf(A.y, x01, v2); v2 = fmaf(B.x, x11, v2); v2 = fmaf(B.w, x21, v2);
                v1 = fmaf(A.x, x01, v1); v1 = fmaf(A.w, x11, v1); v1 = fmaf(B.z, x21, v1);
                v1 = fmaf(A.z, x00, v1); v1 = fmaf(B.y, x10, v1); v1 = fmaf(C,   x20, v1);
                v3 = fmaf(A.x, x02, v3); v3 = fmaf(A.w, x12, v3); v3 = fmaf(B.z, x22, v3);
                v3 = fmaf(A.z, x01, v3); v3 = fmaf(B.y, x11, v3); v3 = fmaf(C,   x21, v3);
            }
        }
        s0 += ex2f(v0); s1 += ex2f(v1); s2 += ex2f(v2); s3 += ex2f(v3);
    }

    int wb = 4 * c;
    op[wb]     = finish(s0, bv);
    op[wb + 1] = finish(s1, bv);
    op[wb + 2] = finish(s2, bv);
    if (wb + 3 < 63) op[wb + 3] = finish(s3, bv);
}

// ---- per-class iteration dispatchers (v14 bodies, blk -> iter index i) ----
__device__ __forceinline__ void iter_cls3(
    int i, const float* x, const float* sw, float* out, float bv, int warp, int lane)
{
    int half = lane >> 4, c = lane & 15;
    int r = (i * 4 + warp) * 2 + half;
    const int per_b = 15 * 31;
    int b = r / per_b; int rem = r - b * per_b;
    int idd = rem / 31; int ihh = rem - idd * 31;
    int od = 2 * idd + 1, oh = 2 * ihh + 1;
    const float* xb = x + (size_t)b * XB;
    float* op = out + ((size_t)(b * 31 + od) * 63 + oh) * 63;
    run_quad22(xb, sw, op, (od + 1) >> 1, (od - 1) >> 1,
               (oh + 1) >> 1, (oh - 1) >> 1, c, bv);
}

template<int CLS>
__device__ __forceinline__ void iter_oct_cls(
    int i, const float* x, const float* sw, float* out, float bv, int warp, int lane)
{
    int rloc = lane >> 3, c = lane & 7;
    int r = i * 16 + warp * 4 + rloc;
    const int pd = (CLS == 2), ph = (CLS == 1);
    const int nhc = ph ? 31 : 32;
    const int per_b = (pd ? 15 : 16) * nhc;
    int b = r / per_b; int rem = r - b * per_b;
    int idd = rem / nhc; int ihh = rem - idd * nhc;
    int od = 2 * idd + pd, oh = 2 * ihh + ph;
    const float* xb = x + (size_t)b * XB;
    float* op = out + ((size_t)(b * 31 + od) * 63 + oh) * 63;
    int id0, id1 = 0, ih0, ih1 = 0;
    if (pd) { id0 = (od + 1) >> 1; id1 = (od - 1) >> 1; } else id0 = od >> 1;
    if (ph) { ih0 = (oh + 1) >> 1; ih1 = (oh - 1) >> 1; } else ih0 = oh >> 1;
    if (CLS == 0)      run_oct<1, 1>(xb, sw, op, id0, id1, ih0, ih1, c, bv);
    else if (CLS == 1) run_oct<1, 2>(xb, sw, op, id0, id1, ih0, ih1, c, bv);
    else               run_oct<2, 1>(xb, sw, op, id0, id1, ih0, ih1, c, bv);
}

// Persistent work-stealing kernel. Class chosen by %smid (SM-ranges sized by
// class workload) -> all CTAs co-resident on an SM run ONE unrolled body (I$
// purity; R15 showed mixing costs 20us). Per-class atomic counters give perfect
// balance; steal phase guarantees completion regardless of placement/SM count.
__global__ __launch_bounds__(128, 8)
void convT_lse_v17(const float* __restrict__ x,
                   const float* __restrict__ bias, float* __restrict__ out)
{
    __shared__ __align__(16) float sw[WSH];
    {   // branch-free prologue: copy prepacked weights (432 float4)
        const float4* src = (const float4*)g_sw;
        float4* dst = (float4*)sw;
        for (int i = threadIdx.x; i < WSH / 4; i += 128) dst[i] = src[i];
    }
    __syncthreads();

    int tid = threadIdx.x, warp = tid >> 5, lane = tid & 31;
    float bv = __ldg(bias);

    unsigned smid;
    asm("mov.u32 %0, %%smid;" : "=r"(smid));
    // SM partition sized by class work (units: cls3 1860, cls2 960, cls1 992,
    // cls0 512 equivalent): 68 / 33 / 33 / rest SMs.
    int mycls = (smid < 68) ? 3 : (smid < 101) ? 2 : (smid < 134) ? 1 : 0;

    __shared__ int s_i;
    // Drain own class first (I$ pure), then steal remaining classes.
    int c = mycls;
    #pragma unroll 1
    for (int k = 0; k < 4; k++) {
        const int lim = (c == 3) ? N3 : (c == 2) ? N2 : (c == 1) ? N1 : N0;
        while (true) {
            if (tid == 0) s_i = atomicAdd(&g_ctr[c], 1);
            __syncthreads();
            int i = s_i;
            __syncthreads();
            if (i >= lim) break;
            if (c == 3)      iter_cls3(i, x, sw, out, bv, warp, lane);
            else if (c == 2) iter_oct_cls<2>(i, x, sw, out, bv, warp, lane);
            else if (c == 1) iter_oct_cls<1>(i, x, sw, out, bv, warp, lane);
            else             iter_oct_cls<0>(i, x, sw, out, bv, warp, lane);
        }
        c = (c + 3) & 3;   // rotate to next class for stealing
    }
}

extern "C" void kernel_launch(void* const* d_in, const int* in_sizes, int n_in,
                              void* d_out, int out_size)
{
    const float* x    = (const float*)d_in[0];
    const float* w    = (const float*)d_in[1];
    const float* bias = (const float*)d_in[2];
    float* out        = (float*)d_out;

    convT_prep<<<1, 128>>>(w);
    convT_lse_v17<<<1216, 128>>>(x, bias, out);
}